// round 9
// baseline (speedup 1.0000x reference)
#include <cuda_runtime.h>
#include <cuda_fp16.h>
#include <cstdint>

#define NSEQ 24
#define NBAT 16
#define NNOD 1024
#define HD   64
#define BH   1024
#define TOT  1048576

// dynamic smem byte offsets
#define OFF_A   0        /* GEMM1 A dbl buf: 2 x 128row x 48B = 12288 */
#define OFF_BT  12288    /* GEMM1 B^T dbl buf: 2 x 128col x 36B = 9216 */
#define OFF_SS  21504    /* sup half 128 x 272B = 34816 */
#define OFF_WT  56320    /* W_g^T half 256 x 272B = 69632 */
#define OFF_PR  125952   /* bg 256f | gam1 64f | bet1 64f = 1536B */
#define SMEMB   127488

__device__ __half g_adj_h[NNOD * NNOD];       // normalized adjacency, fp16
__device__ __half g_wgT_h[2 * 256 * 128];     // W_g transposed [l][gate][k], fp16
__device__ float  g_pe[NSEQ * HD];
__device__ float  g_z0[(size_t)NSEQ * TOT];   // (s,n,b,h)
__device__ float  g_z1[TOT];
__device__ float  g_h0[2][TOT];
__device__ float  g_h1[2][TOT];
__device__ float  g_c0[TOT];
__device__ float  g_c1[TOT];

__device__ __forceinline__ float sigm(float x) { return 1.0f / (1.0f + expf(-x)); }

__device__ __forceinline__ void hmma(float* c, const unsigned* a, const unsigned* b) {
    asm("mma.sync.aligned.m16n8k16.row.col.f32.f16.f16.f32 "
        "{%0,%1,%2,%3},{%4,%5,%6,%7},{%8,%9},{%0,%1,%2,%3};"
        : "+f"(c[0]), "+f"(c[1]), "+f"(c[2]), "+f"(c[3])
        : "r"(a[0]), "r"(a[1]), "r"(a[2]), "r"(a[3]), "r"(b[0]), "r"(b[1]));
}

// ---------------- prep ----------------
__global__ void __launch_bounds__(256) adj_norm_kernel(const float* __restrict__ adj) {
    int m = blockIdx.x, tid = threadIdx.x;
    __shared__ float red[8];
    float s = 0.f;
    for (int j = tid; j < NNOD; j += 256) s += adj[m * NNOD + j];
    for (int o = 16; o; o >>= 1) s += __shfl_xor_sync(0xffffffffu, s, o);
    if ((tid & 31) == 0) red[tid >> 5] = s;
    __syncthreads();
    if (tid < 8) {
        float v = red[tid];
        for (int o = 4; o; o >>= 1) v += __shfl_xor_sync(0xffu, v, o);
        if (tid == 0) red[0] = v;
    }
    __syncthreads();
    float inv = 1.0f / (red[0] + 1e-8f);
    for (int j = tid; j < NNOD; j += 256)
        g_adj_h[m * NNOD + j] = __float2half_rn(adj[m * NNOD + j] * inv);
}

__global__ void __launch_bounds__(256) wgcvt_kernel(const float* __restrict__ Wg) {
    int i = blockIdx.x * 256 + threadIdx.x;          // l*32768 + k*256 + g
    int l = i >> 15, r = i & 32767, k = r >> 8, g = r & 255;
    g_wgT_h[l * 32768 + g * 128 + k] = __float2half_rn(Wg[i]);
}

__global__ void __launch_bounds__(256) zero_kernel() {
    int i = blockIdx.x * 256 + threadIdx.x;
    g_h0[0][i] = 0.f; g_h1[0][i] = 0.f; g_c0[i] = 0.f; g_c1[i] = 0.f;
}

__global__ void __launch_bounds__(256) pe_kernel() {
    int i = blockIdx.x * 256 + threadIdx.x;
    if (i < NSEQ * HD) {
        int s = i >> 6, h = i & 63;
        float ang = (float)s * expf(-(float)(h & ~1) * (9.210340371976184f / 64.0f));
        g_pe[i] = (h & 1) ? cosf(ang) : sinf(ang);
    }
}

__global__ void __launch_bounds__(256) proj_kernel(
    const float* __restrict__ x, const float* __restrict__ Win,
    const float* __restrict__ bin, const float* __restrict__ nemb,
    const float* __restrict__ gam, const float* __restrict__ bet)
{
    __shared__ float sW[512], sB[64];
    int tid = threadIdx.x;
    sW[tid] = Win[tid]; sW[tid + 256] = Win[tid + 256];
    if (tid < 64) sB[tid] = bin[tid];
    __syncthreads();
    int rid = blockIdx.x * 8 + (tid >> 5), lane = tid & 31;
    int n = rid & 1023, s = (rid >> 10) % NSEQ, b = rid / (1024 * NSEQ);
    const float* xr = x + (size_t)rid * 8;
    float xd[8];
#pragma unroll
    for (int d = 0; d < 8; d++) xd[d] = xr[d];
    float v[2];
#pragma unroll
    for (int p = 0; p < 2; p++) {
        int h = lane + 32 * p;
        float acc = sB[h] + g_pe[s * 64 + h];
#pragma unroll
        for (int d = 0; d < 8; d++) acc = fmaf(xd[d], sW[d * 64 + h], acc);
        v[p] = acc;
    }
    float s1 = v[0] + v[1], s2 = v[0] * v[0] + v[1] * v[1];
    for (int o = 16; o; o >>= 1) {
        s1 += __shfl_xor_sync(0xffffffffu, s1, o);
        s2 += __shfl_xor_sync(0xffffffffu, s2, o);
    }
    float mean = s1 * (1.0f / 64.0f);
    float rs = rsqrtf(s2 * (1.0f / 64.0f) - mean * mean + 1e-5f);
#pragma unroll
    for (int p = 0; p < 2; p++) {
        int h = lane + 32 * p;
        g_z0[(((size_t)s * NNOD + n) * NBAT + b) * HD + h] =
            (v[p] - mean) * rs * gam[h] + bet[h] + nemb[n * 64 + h];
    }
}

// ---------------- fused per-(t,layer) fp16 mma kernel ----------------
template <int LAYER>
__global__ void __launch_bounds__(256, 1) layer_fk(
    int t, int pp, const float* __restrict__ bg_all,
    const float* __restrict__ gam_all, const float* __restrict__ bet_all,
    const float* __restrict__ nemb, float* __restrict__ out)
{
    extern __shared__ char smc[];
    float* smf = (float*)smc;
    const int tid = threadIdx.x, lane = tid & 31, wid = tid >> 5;
    const int gid = lane >> 2, tig = lane & 3;
    const int m0 = blockIdx.x * 128, b = blockIdx.y;

    const float* zsrc  = (LAYER == 0) ? (g_z0 + (size_t)t * TOT) : g_z1;
    const float* hprev = (LAYER == 0) ? g_h0[pp] : g_h1[pp];
    float* hdst        = (LAYER == 0) ? g_h0[pp ^ 1] : g_h1[pp ^ 1];
    float* cst         = (LAYER == 0) ? g_c0 : g_c1;

    smf[OFF_PR / 4 + tid] = bg_all[LAYER * 256 + tid];
    if (LAYER == 0 && tid < 128)
        smf[OFF_PR / 4 + 256 + tid] = (tid < 64) ? gam_all[64 + tid] : bet_all[tid];

    // ---- GEMM1: sup(128x128) = adj @ [z|h], K=1024, 64 chunks of 16 ----
    const int ar = tid >> 1, ak = (tid & 1) * 8;           // A loader
    const __half* pA = g_adj_h + (size_t)(m0 + ar) * NNOD + ak;
    const int br = tid >> 4, bc = (tid & 15) * 4;          // B loader
    const float* pZ = zsrc  + (size_t)br * BH + b * HD + bc;
    const float* pH = hprev + (size_t)br * BH + b * HD + bc;

    uint4  rA[2];
    float4 rZ[2], rH[2];
    rA[0] = *(const uint4*)pA;              rA[1] = *(const uint4*)(pA + 16);
    rZ[0] = *(const float4*)pZ;             rZ[1] = *(const float4*)(pZ + 16 * BH);
    rH[0] = *(const float4*)pH;             rH[1] = *(const float4*)(pH + 16 * BH);

    float acc[2][8][4];
#pragma unroll
    for (int a = 0; a < 2; a++)
#pragma unroll
        for (int j = 0; j < 8; j++)
#pragma unroll
            for (int e = 0; e < 4; e++) acc[a][j][e] = 0.f;

    const int wm = wid & 3, wn = wid >> 2;
    const int mrow = wm * 32, ncol = wn * 64;

#pragma unroll 1
    for (int kt = 0; kt < 64; ++kt) {
        const int cur = kt & 1;
        char* As = smc + OFF_A + cur * 6144;
        char* Bt = smc + OFF_BT + cur * 4608;
        *(uint4*)(As + ar * 48 + ak * 2) = rA[cur];
#pragma unroll
        for (int e = 0; e < 4; e++) {
            ((__half*)(Bt + (bc + e) * 36))[br]      = __float2half_rn(((const float*)&rZ[cur])[e]);
            ((__half*)(Bt + (64 + bc + e) * 36))[br] = __float2half_rn(((const float*)&rH[cur])[e]);
        }
        __syncthreads();
        if (kt < 62) {
            int ko = (kt + 2) * 16;
            rA[cur] = *(const uint4*)(pA + ko);
            rZ[cur] = *(const float4*)(pZ + (size_t)ko * BH);
            rH[cur] = *(const float4*)(pH + (size_t)ko * BH);
        }
        unsigned af[2][4], bf[2];
#pragma unroll
        for (int a = 0; a < 2; a++) {
            int r = mrow + a * 16 + gid;
            af[a][0] = *(const unsigned*)(As + r * 48 + tig * 4);
            af[a][1] = *(const unsigned*)(As + (r + 8) * 48 + tig * 4);
            af[a][2] = *(const unsigned*)(As + r * 48 + 16 + tig * 4);
            af[a][3] = *(const unsigned*)(As + (r + 8) * 48 + 16 + tig * 4);
        }
#pragma unroll
        for (int j = 0; j < 8; j++) {
            int n = ncol + j * 8 + gid;
            bf[0] = *(const unsigned*)(Bt + n * 36 + tig * 4);
            bf[1] = *(const unsigned*)(Bt + n * 36 + 16 + tig * 4);
            hmma(acc[0][j], af[0], bf);
            hmma(acc[1][j], af[1], bf);
        }
        __syncthreads();
    }

    // ---- stream W_g^T into smem ----
    {
        const __half* wrow = g_wgT_h + LAYER * 32768 + tid * 128;
        char* W = smc + OFF_WT + tid * 272;
#pragma unroll
        for (int q = 0; q < 16; q++)
            *(uint4*)(W + q * 16) = *(const uint4*)(wrow + q * 8);
    }
    // ---- sup -> smem as fp16 ----
    char* Ss = smc + OFF_SS;
#pragma unroll
    for (int a = 0; a < 2; a++)
#pragma unroll
        for (int j = 0; j < 8; j++) {
            int r = mrow + a * 16 + gid, c = ncol + j * 8 + tig * 2;
            *(__half2*)(Ss + r * 272 + c * 2)       = __floats2half2_rn(acc[a][j][0], acc[a][j][1]);
            *(__half2*)(Ss + (r + 8) * 272 + c * 2) = __floats2half2_rn(acc[a][j][2], acc[a][j][3]);
        }
    __syncthreads();

    // ---- GEMM2: gates(128x256) = sup @ W_g, K=128 ----
    float acc2[32][4];
#pragma unroll
    for (int j = 0; j < 32; j++)
#pragma unroll
        for (int e = 0; e < 4; e++) acc2[j][e] = 0.f;

    const int w2row = wid * 16;
    const char* W0 = smc + OFF_WT;
#pragma unroll 1
    for (int ks = 0; ks < 8; ++ks) {
        unsigned af[4], bf[2];
        int r = w2row + gid, kb = ks * 32;
        af[0] = *(const unsigned*)(Ss + r * 272 + kb + tig * 4);
        af[1] = *(const unsigned*)(Ss + (r + 8) * 272 + kb + tig * 4);
        af[2] = *(const unsigned*)(Ss + r * 272 + kb + 16 + tig * 4);
        af[3] = *(const unsigned*)(Ss + (r + 8) * 272 + kb + 16 + tig * 4);
#pragma unroll
        for (int j = 0; j < 32; j++) {
            int n = j * 8 + gid;
            bf[0] = *(const unsigned*)(W0 + n * 272 + kb + tig * 4);
            bf[1] = *(const unsigned*)(W0 + n * 272 + kb + 16 + tig * 4);
            hmma(acc2[j], af, bf);
        }
    }

    // ---- LSTM pointwise + epilogue ----
    const float* bgs = smf + OFF_PR / 4;
    float hv[2][8][2];
#pragma unroll
    for (int j2 = 0; j2 < 8; ++j2) {
        int hc = j2 * 8 + tig * 2;
#pragma unroll
        for (int a = 0; a < 2; ++a) {
            int r = w2row + gid + a * 8;
            int n = m0 + r;
            size_t base = ((size_t)n * NBAT + b) * HD + hc;
            float2 cp = *(const float2*)&cst[base];
            float cn[2], hn[2];
#pragma unroll
            for (int e = 0; e < 2; ++e) {
                float ig = acc2[j2][a * 2 + e]      + bgs[hc + e];
                float fg = acc2[j2 + 8][a * 2 + e]  + bgs[64 + hc + e];
                float gg = acc2[j2 + 16][a * 2 + e] + bgs[128 + hc + e];
                float og = acc2[j2 + 24][a * 2 + e] + bgs[192 + hc + e];
                float cprev = e ? cp.y : cp.x;
                float c_new = sigm(fg) * cprev + sigm(ig) * tanhf(gg);
                float h_new = sigm(og) * tanhf(c_new);
                cn[e] = c_new; hn[e] = h_new;
            }
            if (LAYER == 1) {
                float2 rd = *(const float2*)&g_h0[pp ^ 1][base];
                hn[0] += rd.x; hn[1] += rd.y;
            }
            *(float2*)&cst[base]  = make_float2(cn[0], cn[1]);
            *(float2*)&hdst[base] = make_float2(hn[0], hn[1]);
            if (LAYER == 1) {
                size_t ob = (((size_t)b * NSEQ + t) * NNOD + n) * HD + hc;
                *(float2*)&out[ob] = make_float2(hn[0], hn[1]);
            }
            hv[a][j2][0] = hn[0]; hv[a][j2][1] = hn[1];
        }
    }

    if (LAYER == 0) {
#pragma unroll
        for (int a = 0; a < 2; ++a) {
            float s1 = 0.f, s2 = 0.f;
#pragma unroll
            for (int j2 = 0; j2 < 8; ++j2) {
                s1 += hv[a][j2][0] + hv[a][j2][1];
                s2 += hv[a][j2][0] * hv[a][j2][0] + hv[a][j2][1] * hv[a][j2][1];
            }
            s1 += __shfl_xor_sync(0xffffffffu, s1, 1);
            s1 += __shfl_xor_sync(0xffffffffu, s1, 2);
            s2 += __shfl_xor_sync(0xffffffffu, s2, 1);
            s2 += __shfl_xor_sync(0xffffffffu, s2, 2);
            float mean = s1 * (1.0f / 64.0f);
            float rs = rsqrtf(s2 * (1.0f / 64.0f) - mean * mean + 1e-5f);
            int n = m0 + w2row + gid + a * 8;
#pragma unroll
            for (int j2 = 0; j2 < 8; ++j2) {
                int hc = j2 * 8 + tig * 2;
                float2 ne = *(const float2*)&nemb[n * HD + hc];
                float z0v = (hv[a][j2][0] - mean) * rs * bgs[256 + hc] + bgs[320 + hc] + ne.x;
                float z1v = (hv[a][j2][1] - mean) * rs * bgs[256 + hc + 1] + bgs[320 + hc + 1] + ne.y;
                *(float2*)&g_z1[((size_t)n * NBAT + b) * HD + hc] = make_float2(z0v, z1v);
            }
        }
    }
}

// ---------------- launch ----------------
extern "C" void kernel_launch(void* const* d_in, const int* in_sizes, int n_in,
                              void* d_out, int out_size) {
    (void)in_sizes; (void)n_in; (void)out_size;
    const float* x    = (const float*)d_in[0];
    const float* adj  = (const float*)d_in[1];
    const float* Win  = (const float*)d_in[2];
    const float* bin  = (const float*)d_in[3];
    const float* nemb = (const float*)d_in[4];
    const float* gam  = (const float*)d_in[5];
    const float* bet  = (const float*)d_in[6];
    const float* Wg   = (const float*)d_in[7];
    const float* bg   = (const float*)d_in[8];
    float* out = (float*)d_out;

    cudaFuncSetAttribute((const void*)layer_fk<0>,
                         cudaFuncAttributeMaxDynamicSharedMemorySize, SMEMB);
    cudaFuncSetAttribute((const void*)layer_fk<1>,
                         cudaFuncAttributeMaxDynamicSharedMemorySize, SMEMB);

    adj_norm_kernel<<<NNOD, 256>>>(adj);
    wgcvt_kernel<<<(2 * 128 * 256) / 256, 256>>>(Wg);
    zero_kernel<<<TOT / 256, 256>>>();
    pe_kernel<<<6, 256>>>();
    proj_kernel<<<(NBAT * NSEQ * NNOD) / 8, 256>>>(x, Win, bin, nemb, gam, bet);

    dim3 grid(8, NBAT);
    for (int t = 0; t < NSEQ; ++t) {
        int pp = t & 1;
        layer_fk<0><<<grid, 256, SMEMB>>>(t, pp, bg, gam, bet, nemb, out);
        layer_fk<1><<<grid, 256, SMEMB>>>(t, pp, bg, gam, bet, nemb, out);
    }
}

// round 11
// speedup vs baseline: 1.7641x; 1.7641x over previous
#include <cuda_runtime.h>
#include <cuda_fp16.h>
#include <cstdint>

#define NSEQ 24
#define NBAT 16
#define NNOD 1024
#define HD   64
#define TOT  1048576
#define FEAT 1048576          /* 16*64*1024 halves */

// dynamic smem byte offsets
#define OFF_A  0              /* 2 x 128x80B = 20480 */
#define OFF_B  20480          /* 2 x 128x80B -> 40960 */
#define OFF_F0 0              /* 64x272B = 17408 (overlays A/B after GEMM1) */
#define OFF_F1 17408          /* -> 34816 */
#define OFF_SS 40960          /* 128x272B = 34816 -> 75776 */
#define OFF_WT 75776          /* 256x272B = 69632 -> 145408 */
#define OFF_PR 145408         /* bg 256f | gam1 64f | bet1 64f = 1536B */
#define SMEMB  146944

__device__ __half g_adj_h[NNOD * NNOD];        // normalized adjacency fp16 [m][k]
__device__ __half g_wgT_h[2 * 256 * 128];      // W_g^T fp16 [l][gate][k]
__device__ float  g_pe[NSEQ * HD];
__device__ __half g_z0F[(size_t)NSEQ * FEAT];  // [s][b][h][n] fp16
__device__ __half g_z1F[FEAT];                 // [b][h][n]
__device__ __half g_h0F[2][FEAT];              // ping-pong feat feed, layer0
__device__ __half g_h1F[2][FEAT];              // ping-pong feat feed, layer1
__device__ float  g_h0r[TOT];                  // fp32 h0 for residual [n][b][h]
__device__ float  g_c0[TOT];
__device__ float  g_c1[TOT];

__device__ __forceinline__ float sigm(float x) { return 1.0f / (1.0f + expf(-x)); }
__device__ __forceinline__ void hmma(float* c, const unsigned* a, const unsigned* b) {
    asm("mma.sync.aligned.m16n8k16.row.col.f32.f16.f16.f32 "
        "{%0,%1,%2,%3},{%4,%5,%6,%7},{%8,%9},{%0,%1,%2,%3};"
        : "+f"(c[0]), "+f"(c[1]), "+f"(c[2]), "+f"(c[3])
        : "r"(a[0]), "r"(a[1]), "r"(a[2]), "r"(a[3]), "r"(b[0]), "r"(b[1]));
}

// ---------------- prep ----------------
__global__ void __launch_bounds__(256) adj_norm_kernel(const float* __restrict__ adj) {
    int m = blockIdx.x, tid = threadIdx.x;
    __shared__ float red[8];
    float s = 0.f;
    for (int j = tid; j < NNOD; j += 256) s += adj[m * NNOD + j];
    for (int o = 16; o; o >>= 1) s += __shfl_xor_sync(0xffffffffu, s, o);
    if ((tid & 31) == 0) red[tid >> 5] = s;
    __syncthreads();
    if (tid < 8) {
        float v = red[tid];
        for (int o = 4; o; o >>= 1) v += __shfl_xor_sync(0xffu, v, o);
        if (tid == 0) red[0] = v;
    }
    __syncthreads();
    float inv = 1.0f / (red[0] + 1e-8f);
    for (int j = tid; j < NNOD; j += 256)
        g_adj_h[m * NNOD + j] = __float2half_rn(adj[m * NNOD + j] * inv);
}

__global__ void __launch_bounds__(256) wgcvt_kernel(const float* __restrict__ Wg) {
    int i = blockIdx.x * 256 + threadIdx.x;        // l*32768 + k*256 + g
    int l = i >> 15, r = i & 32767, k = r >> 8, g = r & 255;
    g_wgT_h[l * 32768 + g * 128 + k] = __float2half_rn(Wg[i]);
}

__global__ void __launch_bounds__(256) zero_kernel() {
    int i = blockIdx.x * 256 + threadIdx.x;
    g_c0[i] = 0.f; g_c1[i] = 0.f;
    g_h0F[0][i] = __ushort_as_half(0); g_h1F[0][i] = __ushort_as_half(0);
}

__global__ void __launch_bounds__(256) pe_kernel() {
    int i = blockIdx.x * 256 + threadIdx.x;
    if (i < NSEQ * HD) {
        int s = i >> 6, h = i & 63;
        float ang = (float)s * expf(-(float)(h & ~1) * (9.210340371976184f / 64.0f));
        g_pe[i] = (h & 1) ? cosf(ang) : sinf(ang);
    }
}

// proj + PE + LN0 + node_embed -> fp16 transposed z0 [s][b][h][n]
__global__ void __launch_bounds__(256) proj_kernel(
    const float* __restrict__ x, const float* __restrict__ Win,
    const float* __restrict__ bin, const float* __restrict__ nemb,
    const float* __restrict__ gam, const float* __restrict__ bet)
{
    __shared__ float sW[512], sB[64];
    __shared__ __align__(16) __half sP[640];       // [64 h][8 n] stride 10
    int tid = threadIdx.x;
    sW[tid] = Win[tid]; sW[tid + 256] = Win[tid + 256];
    if (tid < 64) sB[tid] = bin[tid];
    __syncthreads();
    int w = tid >> 5, lane = tid & 31;
    int rid = blockIdx.x * 8 + w;
    int n = rid & 1023, s = (rid >> 10) % NSEQ, b = rid / (1024 * NSEQ);
    const float* xr = x + (size_t)rid * 8;
    float xd[8];
#pragma unroll
    for (int d = 0; d < 8; d++) xd[d] = xr[d];
    float v[2];
#pragma unroll
    for (int p = 0; p < 2; p++) {
        int h = lane + 32 * p;
        float acc = sB[h] + g_pe[s * 64 + h];
#pragma unroll
        for (int d = 0; d < 8; d++) acc = fmaf(xd[d], sW[d * 64 + h], acc);
        v[p] = acc;
    }
    float s1 = v[0] + v[1], s2 = v[0] * v[0] + v[1] * v[1];
    for (int o = 16; o; o >>= 1) {
        s1 += __shfl_xor_sync(0xffffffffu, s1, o);
        s2 += __shfl_xor_sync(0xffffffffu, s2, o);
    }
    float mean = s1 * (1.0f / 64.0f);
    float rs = rsqrtf(s2 * (1.0f / 64.0f) - mean * mean + 1e-5f);
#pragma unroll
    for (int p = 0; p < 2; p++) {
        int h = lane + 32 * p;
        float z = (v[p] - mean) * rs * gam[h] + bet[h] + nemb[n * 64 + h];
        sP[h * 10 + w] = __float2half_rn(z);
    }
    __syncthreads();
    int h = tid >> 2, np = tid & 3;
    int rid0 = blockIdx.x * 8;
    int n0 = rid0 & 1023, s0 = (rid0 >> 10) % NSEQ, b0 = rid0 / (1024 * NSEQ);
    *(unsigned*)&g_z0F[((size_t)(s0 * 16 + b0) * 64 + h) * 1024 + n0 + np * 2] =
        *(const unsigned*)&sP[h * 10 + np * 2];
}

// ---------------- fused per-(t,layer) fp16 mma kernel ----------------
template <int LAYER>
__global__ void __launch_bounds__(256, 1) layer_fk(
    int t, int pp, const float* __restrict__ bg_all,
    const float* __restrict__ gam_all, const float* __restrict__ bet_all,
    const float* __restrict__ nemb, float* __restrict__ out)
{
    extern __shared__ char smc[];
    float* smf = (float*)smc;
    const int tid = threadIdx.x, lane = tid & 31, wid = tid >> 5;
    const int gid = lane >> 2, tig = lane & 3;
    const int m0 = blockIdx.x * 128, b = blockIdx.y;

    float* cst = (LAYER == 0) ? g_c0 : g_c1;

    smf[OFF_PR / 4 + tid] = bg_all[LAYER * 256 + tid];
    if (LAYER == 0 && tid < 128)
        smf[OFF_PR / 4 + 256 + tid] = (tid < 64) ? gam_all[64 + tid] : bet_all[tid];

    // W_g^T -> smem (once)
    {
        const __half* wrow = g_wgT_h + LAYER * 32768 + tid * 128;
        char* W = smc + OFF_WT + tid * 272;
#pragma unroll
        for (int q = 0; q < 16; q++)
            *(uint4*)(W + q * 16) = *(const uint4*)(wrow + q * 8);
    }

    // ---- GEMM1: sup(128x128) = adj @ feat^T, K=1024, 32 chunks of 32 ----
    const int ar = tid >> 1, kh = tid & 1;                  // row/col 0..127, k-half
    const __half* pA = g_adj_h + (size_t)(m0 + ar) * 1024 + kh * 16;
    const __half* pB;
    if (LAYER == 0)
        pB = (ar < 64) ? g_z0F + ((size_t)(t * 16 + b) * 64 + ar) * 1024 + kh * 16
                       : g_h0F[pp] + ((size_t)b * 64 + (ar - 64)) * 1024 + kh * 16;
    else
        pB = (ar < 64) ? g_z1F + ((size_t)b * 64 + ar) * 1024 + kh * 16
                       : g_h1F[pp] + ((size_t)b * 64 + (ar - 64)) * 1024 + kh * 16;

    uint4 pa0, pa1, pb0, pb1;
    pa0 = *(const uint4*)pA;        pa1 = *(const uint4*)(pA + 8);
    pb0 = *(const uint4*)pB;        pb1 = *(const uint4*)(pB + 8);
    {
        char* An = smc + OFF_A, *Bn = smc + OFF_B;
        *(uint4*)(An + ar * 80 + kh * 32) = pa0;
        *(uint4*)(An + ar * 80 + kh * 32 + 16) = pa1;
        *(uint4*)(Bn + ar * 80 + kh * 32) = pb0;
        *(uint4*)(Bn + ar * 80 + kh * 32 + 16) = pb1;
    }
    __syncthreads();

    float acc[2][8][4];
#pragma unroll
    for (int a = 0; a < 2; a++)
#pragma unroll
        for (int j = 0; j < 8; j++)
#pragma unroll
            for (int e = 0; e < 4; e++) acc[a][j][e] = 0.f;

    const int wm = wid & 3, wn = wid >> 2;
    const int mrow = wm * 32, ncol = wn * 64;

#pragma unroll 1
    for (int kt = 0; kt < 32; ++kt) {
        if (kt < 31) {
            int ko = (kt + 1) * 32;
            pa0 = *(const uint4*)(pA + ko);  pa1 = *(const uint4*)(pA + ko + 8);
            pb0 = *(const uint4*)(pB + ko);  pb1 = *(const uint4*)(pB + ko + 8);
        }
        const char* As = smc + OFF_A + (kt & 1) * 10240;
        const char* Bs = smc + OFF_B + (kt & 1) * 10240;
#pragma unroll
        for (int ks = 0; ks < 2; ++ks) {
            unsigned af[2][4], bf[2];
            int kb = ks * 32;
#pragma unroll
            for (int a = 0; a < 2; a++) {
                int r = mrow + a * 16 + gid;
                af[a][0] = *(const unsigned*)(As + r * 80 + kb + tig * 4);
                af[a][1] = *(const unsigned*)(As + (r + 8) * 80 + kb + tig * 4);
                af[a][2] = *(const unsigned*)(As + r * 80 + kb + 16 + tig * 4);
                af[a][3] = *(const unsigned*)(As + (r + 8) * 80 + kb + 16 + tig * 4);
            }
#pragma unroll
            for (int j = 0; j < 8; j++) {
                int n = ncol + j * 8 + gid;
                bf[0] = *(const unsigned*)(Bs + n * 80 + kb + tig * 4);
                bf[1] = *(const unsigned*)(Bs + n * 80 + kb + 16 + tig * 4);
                hmma(acc[0][j], af[0], bf);
                hmma(acc[1][j], af[1], bf);
            }
        }
        if (kt < 31) {
            char* An = smc + OFF_A + ((kt + 1) & 1) * 10240;
            char* Bn = smc + OFF_B + ((kt + 1) & 1) * 10240;
            *(uint4*)(An + ar * 80 + kh * 32) = pa0;
            *(uint4*)(An + ar * 80 + kh * 32 + 16) = pa1;
            *(uint4*)(Bn + ar * 80 + kh * 32) = pb0;
            *(uint4*)(Bn + ar * 80 + kh * 32 + 16) = pb1;
            __syncthreads();
        }
    }

    // ---- sup -> smem fp16 ----
    char* Ss = smc + OFF_SS;
#pragma unroll
    for (int a = 0; a < 2; a++)
#pragma unroll
        for (int j = 0; j < 8; j++) {
            int r = mrow + a * 16 + gid, c = ncol + j * 8 + tig * 2;
            *(__half2*)(Ss + r * 272 + c * 2)       = __floats2half2_rn(acc[a][j][0], acc[a][j][1]);
            *(__half2*)(Ss + (r + 8) * 272 + c * 2) = __floats2half2_rn(acc[a][j][2], acc[a][j][3]);
        }
    __syncthreads();

    // ---- GEMM2: gates(128x256) = sup @ W_g, K=128, no barriers ----
    float acc2[32][4];
#pragma unroll
    for (int j = 0; j < 32; j++)
#pragma unroll
        for (int e = 0; e < 4; e++) acc2[j][e] = 0.f;

    const int w2row = wid * 16;
    const char* W0 = smc + OFF_WT;
#pragma unroll 1
    for (int ks = 0; ks < 8; ++ks) {
        unsigned af[4], bf[2];
        int r = w2row + gid, kb = ks * 32;
        af[0] = *(const unsigned*)(Ss + r * 272 + kb + tig * 4);
        af[1] = *(const unsigned*)(Ss + (r + 8) * 272 + kb + tig * 4);
        af[2] = *(const unsigned*)(Ss + r * 272 + kb + 16 + tig * 4);
        af[3] = *(const unsigned*)(Ss + (r + 8) * 272 + kb + 16 + tig * 4);
#pragma unroll
        for (int j = 0; j < 32; j++) {
            int n = j * 8 + gid;
            bf[0] = *(const unsigned*)(W0 + n * 272 + kb + tig * 4);
            bf[1] = *(const unsigned*)(W0 + n * 272 + kb + 16 + tig * 4);
            hmma(acc2[j], af, bf);
        }
    }

    // ---- LSTM pointwise + epilogue ----
    const float* bgs = smf + OFF_PR / 4;
    __half* F0 = (__half*)(smc + OFF_F0);
    __half* F1 = (__half*)(smc + OFF_F1);
    float hv[2][8][2];
#pragma unroll
    for (int j2 = 0; j2 < 8; ++j2) {
        int hc = j2 * 8 + tig * 2;
#pragma unroll
        for (int a = 0; a < 2; ++a) {
            int r = w2row + gid + a * 8;
            int n = m0 + r;
            size_t base = ((size_t)n * NBAT + b) * HD + hc;
            float2 cp = *(const float2*)&cst[base];
            float cn[2], hn[2];
#pragma unroll
            for (int e = 0; e < 2; ++e) {
                float ig = acc2[j2][a * 2 + e]      + bgs[hc + e];
                float fg = acc2[j2 + 8][a * 2 + e]  + bgs[64 + hc + e];
                float gg = acc2[j2 + 16][a * 2 + e] + bgs[128 + hc + e];
                float og = acc2[j2 + 24][a * 2 + e] + bgs[192 + hc + e];
                float cprev = e ? cp.y : cp.x;
                float c_new = sigm(fg) * cprev + sigm(ig) * tanhf(gg);
                float h_new = sigm(og) * tanhf(c_new);
                cn[e] = c_new; hn[e] = h_new;
            }
            if (LAYER == 1) {
                float2 rd = *(const float2*)&g_h0r[base];
                hn[0] += rd.x; hn[1] += rd.y;
            }
            *(float2*)&cst[base] = make_float2(cn[0], cn[1]);
            if (LAYER == 0) {
                *(float2*)&g_h0r[base] = make_float2(hn[0], hn[1]);
            } else {
                size_t ob = (((size_t)b * NSEQ + t) * NNOD + n) * HD + hc;
                *(float2*)&out[ob] = make_float2(hn[0], hn[1]);
                F0[hc * 136 + r]       = __float2half_rn(hn[0]);
                F0[(hc + 1) * 136 + r] = __float2half_rn(hn[1]);
            }
            hv[a][j2][0] = hn[0]; hv[a][j2][1] = hn[1];
        }
    }

    if (LAYER == 0) {
        // stage h-feat + LN->z1 feat (both fp16 transposed tiles)
#pragma unroll
        for (int a = 0; a < 2; ++a) {
            float s1 = 0.f, s2 = 0.f;
#pragma unroll
            for (int j2 = 0; j2 < 8; ++j2) {
                s1 += hv[a][j2][0] + hv[a][j2][1];
                s2 += hv[a][j2][0] * hv[a][j2][0] + hv[a][j2][1] * hv[a][j2][1];
            }
            s1 += __shfl_xor_sync(0xffffffffu, s1, 1);
            s1 += __shfl_xor_sync(0xffffffffu, s1, 2);
            s2 += __shfl_xor_sync(0xffffffffu, s2, 1);
            s2 += __shfl_xor_sync(0xffffffffu, s2, 2);
            float mean = s1 * (1.0f / 64.0f);
            float rs = rsqrtf(s2 * (1.0f / 64.0f) - mean * mean + 1e-5f);
            int r = w2row + gid + a * 8;
            int n = m0 + r;
#pragma unroll
            for (int j2 = 0; j2 < 8; ++j2) {
                int hc = j2 * 8 + tig * 2;
                float2 ne = *(const float2*)&nemb[n * HD + hc];
                float z0v = (hv[a][j2][0] - mean) * rs * bgs[256 + hc] + bgs[320 + hc] + ne.x;
                float z1v = (hv[a][j2][1] - mean) * rs * bgs[256 + hc + 1] + bgs[320 + hc + 1] + ne.y;
                F0[hc * 136 + r]       = __float2half_rn(hv[a][j2][0]);
                F0[(hc + 1) * 136 + r] = __float2half_rn(hv[a][j2][1]);
                F1[hc * 136 + r]       = __float2half_rn(z0v);
                F1[(hc + 1) * 136 + r] = __float2half_rn(z1v);
            }
        }
    }
    __syncthreads();

    // flush feat tiles (coalesced, 272B rows)
    {
        __half* d0 = (LAYER == 0) ? g_h0F[pp ^ 1] + (size_t)b * 65536
                                  : g_h1F[pp ^ 1] + (size_t)b * 65536;
#pragma unroll
        for (int i = 0; i < 4; i++) {
            int idx = tid + i * 256, h = idx >> 4, sg = idx & 15;
            *(uint4*)(d0 + ((size_t)h << 10) + m0 + sg * 8) =
                *(const uint4*)(smc + OFF_F0 + h * 272 + sg * 16);
        }
        if (LAYER == 0) {
            __half* d1 = g_z1F + (size_t)b * 65536;
#pragma unroll
            for (int i = 0; i < 4; i++) {
                int idx = tid + i * 256, h = idx >> 4, sg = idx & 15;
                *(uint4*)(d1 + ((size_t)h << 10) + m0 + sg * 8) =
                    *(const uint4*)(smc + OFF_F1 + h * 272 + sg * 16);
            }
        }
    }
}

// ---------------- launch ----------------
extern "C" void kernel_launch(void* const* d_in, const int* in_sizes, int n_in,
                              void* d_out, int out_size) {
    (void)in_sizes; (void)n_in; (void)out_size;
    const float* x    = (const float*)d_in[0];
    const float* adj  = (const float*)d_in[1];
    const float* Win  = (const float*)d_in[2];
    const float* bin  = (const float*)d_in[3];
    const float* nemb = (const float*)d_in[4];
    const float* gam  = (const float*)d_in[5];
    const float* bet  = (const float*)d_in[6];
    const float* Wg   = (const float*)d_in[7];
    const float* bg   = (const float*)d_in[8];
    float* out = (float*)d_out;

    cudaFuncSetAttribute((const void*)layer_fk<0>,
                         cudaFuncAttributeMaxDynamicSharedMemorySize, SMEMB);
    cudaFuncSetAttribute((const void*)layer_fk<1>,
                         cudaFuncAttributeMaxDynamicSharedMemorySize, SMEMB);

    adj_norm_kernel<<<NNOD, 256>>>(adj);
    wgcvt_kernel<<<(2 * 128 * 256) / 256, 256>>>(Wg);
    zero_kernel<<<TOT / 256, 256>>>();
    pe_kernel<<<6, 256>>>();
    proj_kernel<<<(NBAT * NSEQ * NNOD) / 8, 256>>>(x, Win, bin, nemb, gam, bet);

    dim3 grid(8, NBAT);
    for (int t = 0; t < NSEQ; ++t) {
        int pp = t & 1;
        layer_fk<0><<<grid, 256, SMEMB>>>(t, pp, bg, gam, bet, nemb, out);
        layer_fk<1><<<grid, 256, SMEMB>>>(t, pp, bg, gam, bet, nemb, out);
    }
}

// round 12
// speedup vs baseline: 1.7670x; 1.0016x over previous
#include <cuda_runtime.h>
#include <cuda_fp16.h>
#include <cstdint>

#define NSEQ 24
#define NBAT 16
#define NNOD 1024
#define HD   64
#define TOT  1048576
#define FEAT 1048576          /* 16*64*1024 halves */

// dynamic smem byte offsets
#define OFF_A  0              /* 2 x 128x80B = 20480 */
#define OFF_B  20480          /* 2 x 128x80B -> 40960 */
#define OFF_F0 0              /* 64x272B = 17408 (overlays A after GEMM1) */
#define OFF_F1 17408          /* -> 34816 */
#define OFF_WT 40960          /* 256x272B = 69632 -> 110592 */
#define OFF_PR 110592         /* bg 256f | gam1 64f | bet1 64f = 1536B */
#define SMEMB  112128

__device__ __half g_adj_h[NNOD * NNOD];        // normalized adjacency fp16 [m][k]
__device__ __half g_wgT_h[2 * 256 * 128];      // W_g^T fp16 [l][gate][k]
__device__ float  g_pe[NSEQ * HD];
__device__ __half g_z0F[(size_t)NSEQ * FEAT];  // [s][b][h][n] fp16
__device__ __half g_z1F[FEAT];                 // [b][h][n]
__device__ __half g_h0F[2][FEAT];              // ping-pong feat feed, layer0
__device__ __half g_h1F[2][FEAT];              // ping-pong feat feed, layer1
__device__ float  g_h0r[TOT];                  // fp32 h0 for residual [n][b][h]
__device__ float  g_c0[TOT];
__device__ float  g_c1[TOT];

__device__ __forceinline__ float sigm(float x) { return 1.0f / (1.0f + expf(-x)); }
__device__ __forceinline__ void hmma(float* c, const unsigned* a, const unsigned* b) {
    asm("mma.sync.aligned.m16n8k16.row.col.f32.f16.f16.f32 "
        "{%0,%1,%2,%3},{%4,%5,%6,%7},{%8,%9},{%0,%1,%2,%3};"
        : "+f"(c[0]), "+f"(c[1]), "+f"(c[2]), "+f"(c[3])
        : "r"(a[0]), "r"(a[1]), "r"(a[2]), "r"(a[3]), "r"(b[0]), "r"(b[1]));
}
__device__ __forceinline__ void ldsm4(unsigned* r, uint32_t a) {
    asm volatile("ldmatrix.sync.aligned.m8n8.x4.shared.b16 {%0,%1,%2,%3}, [%4];"
        : "=r"(r[0]), "=r"(r[1]), "=r"(r[2]), "=r"(r[3]) : "r"(a));
}
__device__ __forceinline__ uint32_t s2u(const void* p) {
    uint32_t a;
    asm("{ .reg .u64 t; cvta.to.shared.u64 t, %1; cvt.u32.u64 %0, t; }" : "=r"(a) : "l"(p));
    return a;
}
__device__ __forceinline__ unsigned packh2(float x, float y) {
    __half2 h = __floats2half2_rn(x, y);
    return *(unsigned*)&h;
}

// ---------------- prep ----------------
__global__ void __launch_bounds__(256) adj_norm_kernel(const float* __restrict__ adj) {
    int m = blockIdx.x, tid = threadIdx.x;
    __shared__ float red[8];
    float s = 0.f;
    for (int j = tid; j < NNOD; j += 256) s += adj[m * NNOD + j];
    for (int o = 16; o; o >>= 1) s += __shfl_xor_sync(0xffffffffu, s, o);
    if ((tid & 31) == 0) red[tid >> 5] = s;
    __syncthreads();
    if (tid < 8) {
        float v = red[tid];
        for (int o = 4; o; o >>= 1) v += __shfl_xor_sync(0xffu, v, o);
        if (tid == 0) red[0] = v;
    }
    __syncthreads();
    float inv = 1.0f / (red[0] + 1e-8f);
    for (int j = tid; j < NNOD; j += 256)
        g_adj_h[m * NNOD + j] = __float2half_rn(adj[m * NNOD + j] * inv);
}

__global__ void __launch_bounds__(256) wgcvt_kernel(const float* __restrict__ Wg) {
    int i = blockIdx.x * 256 + threadIdx.x;        // l*32768 + k*256 + g
    int l = i >> 15, r = i & 32767, k = r >> 8, g = r & 255;
    g_wgT_h[l * 32768 + g * 128 + k] = __float2half_rn(Wg[i]);
}

__global__ void __launch_bounds__(256) zero_kernel() {
    int i = blockIdx.x * 256 + threadIdx.x;
    g_c0[i] = 0.f; g_c1[i] = 0.f;
    g_h0F[0][i] = __ushort_as_half(0); g_h1F[0][i] = __ushort_as_half(0);
}

__global__ void __launch_bounds__(256) pe_kernel() {
    int i = blockIdx.x * 256 + threadIdx.x;
    if (i < NSEQ * HD) {
        int s = i >> 6, h = i & 63;
        float ang = (float)s * expf(-(float)(h & ~1) * (9.210340371976184f / 64.0f));
        g_pe[i] = (h & 1) ? cosf(ang) : sinf(ang);
    }
}

// proj + PE + LN0 + node_embed -> fp16 transposed z0 [s][b][h][n]
__global__ void __launch_bounds__(256) proj_kernel(
    const float* __restrict__ x, const float* __restrict__ Win,
    const float* __restrict__ bin, const float* __restrict__ nemb,
    const float* __restrict__ gam, const float* __restrict__ bet)
{
    __shared__ float sW[512], sB[64];
    __shared__ __align__(16) __half sP[640];       // [64 h][8 n] stride 10
    int tid = threadIdx.x;
    sW[tid] = Win[tid]; sW[tid + 256] = Win[tid + 256];
    if (tid < 64) sB[tid] = bin[tid];
    __syncthreads();
    int w = tid >> 5, lane = tid & 31;
    int rid = blockIdx.x * 8 + w;
    int n = rid & 1023, s = (rid >> 10) % NSEQ, b = rid / (1024 * NSEQ);
    const float* xr = x + (size_t)rid * 8;
    float xd[8];
#pragma unroll
    for (int d = 0; d < 8; d++) xd[d] = xr[d];
    float v[2];
#pragma unroll
    for (int p = 0; p < 2; p++) {
        int h = lane + 32 * p;
        float acc = sB[h] + g_pe[s * 64 + h];
#pragma unroll
        for (int d = 0; d < 8; d++) acc = fmaf(xd[d], sW[d * 64 + h], acc);
        v[p] = acc;
    }
    float s1 = v[0] + v[1], s2 = v[0] * v[0] + v[1] * v[1];
    for (int o = 16; o; o >>= 1) {
        s1 += __shfl_xor_sync(0xffffffffu, s1, o);
        s2 += __shfl_xor_sync(0xffffffffu, s2, o);
    }
    float mean = s1 * (1.0f / 64.0f);
    float rs = rsqrtf(s2 * (1.0f / 64.0f) - mean * mean + 1e-5f);
#pragma unroll
    for (int p = 0; p < 2; p++) {
        int h = lane + 32 * p;
        float z = (v[p] - mean) * rs * gam[h] + bet[h] + nemb[n * 64 + h];
        sP[h * 10 + w] = __float2half_rn(z);
    }
    __syncthreads();
    int h = tid >> 2, np = tid & 3;
    int rid0 = blockIdx.x * 8;
    int n0 = rid0 & 1023, s0 = (rid0 >> 10) % NSEQ, b0 = rid0 / (1024 * NSEQ);
    *(unsigned*)&g_z0F[((size_t)(s0 * 16 + b0) * 64 + h) * 1024 + n0 + np * 2] =
        *(const unsigned*)&sP[h * 10 + np * 2];
}

// ---------------- fused per-(t,layer) fp16 mma kernel ----------------
// warp tiling: each warp owns m16 x n128 in GEMM1; its C frags become GEMM2 A frags.
template <int LAYER>
__global__ void __launch_bounds__(256, 1) layer_fk(
    int t, int pp, const float* __restrict__ bg_all,
    const float* __restrict__ gam_all, const float* __restrict__ bet_all,
    const float* __restrict__ nemb, float* __restrict__ out)
{
    extern __shared__ char smc[];
    float* smf = (float*)smc;
    const int tid = threadIdx.x, lane = tid & 31, wid = tid >> 5;
    const int gid = lane >> 2, tig = lane & 3;
    const int m0 = blockIdx.x * 128, b = blockIdx.y;
    const uint32_t sb = s2u(smc);

    float* cst = (LAYER == 0) ? g_c0 : g_c1;

    smf[OFF_PR / 4 + tid] = bg_all[LAYER * 256 + tid];
    if (LAYER == 0 && tid < 128)
        smf[OFF_PR / 4 + 256 + tid] = (tid < 64) ? gam_all[64 + tid] : bet_all[tid];

    // W_g^T -> smem (once)
    {
        const __half* wrow = g_wgT_h + LAYER * 32768 + tid * 128;
        char* W = smc + OFF_WT + tid * 272;
#pragma unroll
        for (int q = 0; q < 16; q++)
            *(uint4*)(W + q * 16) = *(const uint4*)(wrow + q * 8);
    }

    // ---- GEMM1: sup(128x128) = adj @ feat^T, K=1024, 32 chunks of 32 ----
    const int ar = tid >> 1, kh = tid & 1;
    const __half* pA = g_adj_h + (size_t)(m0 + ar) * 1024 + kh * 16;
    const __half* pB;
    if (LAYER == 0)
        pB = (ar < 64) ? g_z0F + ((size_t)(t * 16 + b) * 64 + ar) * 1024 + kh * 16
                       : g_h0F[pp] + ((size_t)b * 64 + (ar - 64)) * 1024 + kh * 16;
    else
        pB = (ar < 64) ? g_z1F + ((size_t)b * 64 + ar) * 1024 + kh * 16
                       : g_h1F[pp] + ((size_t)b * 64 + (ar - 64)) * 1024 + kh * 16;

    uint4 pa0, pa1, pb0, pb1;
    pa0 = *(const uint4*)pA;        pa1 = *(const uint4*)(pA + 8);
    pb0 = *(const uint4*)pB;        pb1 = *(const uint4*)(pB + 8);
    {
        char* An = smc + OFF_A, *Bn = smc + OFF_B;
        *(uint4*)(An + ar * 80 + kh * 32) = pa0;
        *(uint4*)(An + ar * 80 + kh * 32 + 16) = pa1;
        *(uint4*)(Bn + ar * 80 + kh * 32) = pb0;
        *(uint4*)(Bn + ar * 80 + kh * 32 + 16) = pb1;
    }
    __syncthreads();

    float acc[16][4];
#pragma unroll
    for (int j = 0; j < 16; j++)
#pragma unroll
        for (int e = 0; e < 4; e++) acc[j][e] = 0.f;

    const int mrow = wid * 16;
    // lane-constant ldmatrix address parts
    const uint32_t aLane = (uint32_t)((mrow + (lane & 15)) * 80 + (lane >> 4) * 16);
    const int nSeg = (lane & 7) + ((lane >> 4) & 1) * 8;
    const int kSeg = ((lane >> 3) & 1) * 16;
    const uint32_t bLane = (uint32_t)(nSeg * 80 + kSeg);
    const uint32_t wLane = (uint32_t)(nSeg * 272 + kSeg);

#pragma unroll 1
    for (int kt = 0; kt < 32; ++kt) {
        if (kt < 31) {
            int ko = (kt + 1) * 32;
            pa0 = *(const uint4*)(pA + ko);  pa1 = *(const uint4*)(pA + ko + 8);
            pb0 = *(const uint4*)(pB + ko);  pb1 = *(const uint4*)(pB + ko + 8);
        }
        const uint32_t Asb = sb + OFF_A + (kt & 1) * 10240;
        const uint32_t Bsb = sb + OFF_B + (kt & 1) * 10240;
#pragma unroll
        for (int ks = 0; ks < 2; ++ks) {
            unsigned af[4];
            ldsm4(af, Asb + aLane + ks * 32);
#pragma unroll
            for (int jp = 0; jp < 8; jp++) {
                unsigned bq[4];
                ldsm4(bq, Bsb + bLane + jp * (16 * 80) + ks * 32);
                hmma(acc[jp * 2], af, bq);
                hmma(acc[jp * 2 + 1], af, bq + 2);
            }
        }
        if (kt < 31) {
            char* An = smc + OFF_A + ((kt + 1) & 1) * 10240;
            char* Bn = smc + OFF_B + ((kt + 1) & 1) * 10240;
            *(uint4*)(An + ar * 80 + kh * 32) = pa0;
            *(uint4*)(An + ar * 80 + kh * 32 + 16) = pa1;
            *(uint4*)(Bn + ar * 80 + kh * 32) = pb0;
            *(uint4*)(Bn + ar * 80 + kh * 32 + 16) = pb1;
            __syncthreads();
        }
    }
    __syncthreads();   // A/B region free for F0/F1 overlay later

    // ---- convert sup C-frags -> GEMM2 A-frags (registers only) ----
    unsigned af2[8][4];
#pragma unroll
    for (int kc = 0; kc < 8; kc++) {
        af2[kc][0] = packh2(acc[2 * kc][0],     acc[2 * kc][1]);
        af2[kc][1] = packh2(acc[2 * kc][2],     acc[2 * kc][3]);
        af2[kc][2] = packh2(acc[2 * kc + 1][0], acc[2 * kc + 1][1]);
        af2[kc][3] = packh2(acc[2 * kc + 1][2], acc[2 * kc + 1][3]);
    }

    // ---- GEMM2: gates(m16 x 256) = sup @ W_g, K=128 ----
    float acc2[32][4];
#pragma unroll
    for (int j = 0; j < 32; j++)
#pragma unroll
        for (int e = 0; e < 4; e++) acc2[j][e] = 0.f;

    const uint32_t Wsb = sb + OFF_WT;
#pragma unroll 1
    for (int kc = 0; kc < 8; ++kc) {
#pragma unroll
        for (int jp = 0; jp < 16; jp++) {
            unsigned bq[4];
            ldsm4(bq, Wsb + wLane + jp * (16 * 272) + kc * 32);
            hmma(acc2[jp * 2], af2[kc], bq);
            hmma(acc2[jp * 2 + 1], af2[kc], bq + 2);
        }
    }

    // ---- LSTM pointwise + epilogue ----
    const float* bgs = smf + OFF_PR / 4;
    __half* F0 = (__half*)(smc + OFF_F0);
    __half* F1 = (__half*)(smc + OFF_F1);
    float hv[2][8][2];
#pragma unroll
    for (int j2 = 0; j2 < 8; ++j2) {
        int hc = j2 * 8 + tig * 2;
#pragma unroll
        for (int a = 0; a < 2; ++a) {
            int r = mrow + gid + a * 8;
            int n = m0 + r;
            size_t base = ((size_t)n * NBAT + b) * HD + hc;
            float2 cp = *(const float2*)&cst[base];
            float cn[2], hn[2];
#pragma unroll
            for (int e = 0; e < 2; ++e) {
                float ig = acc2[j2][a * 2 + e]      + bgs[hc + e];
                float fg = acc2[j2 + 8][a * 2 + e]  + bgs[64 + hc + e];
                float gg = acc2[j2 + 16][a * 2 + e] + bgs[128 + hc + e];
                float og = acc2[j2 + 24][a * 2 + e] + bgs[192 + hc + e];
                float cprev = e ? cp.y : cp.x;
                float c_new = sigm(fg) * cprev + sigm(ig) * tanhf(gg);
                float h_new = sigm(og) * tanhf(c_new);
                cn[e] = c_new; hn[e] = h_new;
            }
            if (LAYER == 1) {
                float2 rd = *(const float2*)&g_h0r[base];
                hn[0] += rd.x; hn[1] += rd.y;
            }
            *(float2*)&cst[base] = make_float2(cn[0], cn[1]);
            if (LAYER == 0) {
                *(float2*)&g_h0r[base] = make_float2(hn[0], hn[1]);
            } else {
                size_t ob = (((size_t)b * NSEQ + t) * NNOD + n) * HD + hc;
                *(float2*)&out[ob] = make_float2(hn[0], hn[1]);
                F0[hc * 136 + r]       = __float2half_rn(hn[0]);
                F0[(hc + 1) * 136 + r] = __float2half_rn(hn[1]);
            }
            hv[a][j2][0] = hn[0]; hv[a][j2][1] = hn[1];
        }
    }

    if (LAYER == 0) {
#pragma unroll
        for (int a = 0; a < 2; ++a) {
            float s1 = 0.f, s2 = 0.f;
#pragma unroll
            for (int j2 = 0; j2 < 8; ++j2) {
                s1 += hv[a][j2][0] + hv[a][j2][1];
                s2 += hv[a][j2][0] * hv[a][j2][0] + hv[a][j2][1] * hv[a][j2][1];
            }
            s1 += __shfl_xor_sync(0xffffffffu, s1, 1);
            s1 += __shfl_xor_sync(0xffffffffu, s1, 2);
            s2 += __shfl_xor_sync(0xffffffffu, s2, 1);
            s2 += __shfl_xor_sync(0xffffffffu, s2, 2);
            float mean = s1 * (1.0f / 64.0f);
            float rs = rsqrtf(s2 * (1.0f / 64.0f) - mean * mean + 1e-5f);
            int r = mrow + gid + a * 8;
            int n = m0 + r;
#pragma unroll
            for (int j2 = 0; j2 < 8; ++j2) {
                int hc = j2 * 8 + tig * 2;
                float2 ne = *(const float2*)&nemb[n * HD + hc];
                float z0v = (hv[a][j2][0] - mean) * rs * bgs[256 + hc] + bgs[320 + hc] + ne.x;
                float z1v = (hv[a][j2][1] - mean) * rs * bgs[256 + hc + 1] + bgs[320 + hc + 1] + ne.y;
                F0[hc * 136 + r]       = __float2half_rn(hv[a][j2][0]);
                F0[(hc + 1) * 136 + r] = __float2half_rn(hv[a][j2][1]);
                F1[hc * 136 + r]       = __float2half_rn(z0v);
                F1[(hc + 1) * 136 + r] = __float2half_rn(z1v);
            }
        }
    }
    __syncthreads();

    // flush feat tiles (coalesced, 272B rows)
    {
        __half* d0 = (LAYER == 0) ? g_h0F[pp ^ 1] + (size_t)b * 65536
                                  : g_h1F[pp ^ 1] + (size_t)b * 65536;
#pragma unroll
        for (int i = 0; i < 4; i++) {
            int idx = tid + i * 256, h = idx >> 4, sg = idx & 15;
            *(uint4*)(d0 + ((size_t)h << 10) + m0 + sg * 8) =
                *(const uint4*)(smc + OFF_F0 + h * 272 + sg * 16);
        }
        if (LAYER == 0) {
            __half* d1 = g_z1F + (size_t)b * 65536;
#pragma unroll
            for (int i = 0; i < 4; i++) {
                int idx = tid + i * 256, h = idx >> 4, sg = idx & 15;
                *(uint4*)(d1 + ((size_t)h << 10) + m0 + sg * 8) =
                    *(const uint4*)(smc + OFF_F1 + h * 272 + sg * 16);
            }
        }
    }
}

// ---------------- launch ----------------
extern "C" void kernel_launch(void* const* d_in, const int* in_sizes, int n_in,
                              void* d_out, int out_size) {
    (void)in_sizes; (void)n_in; (void)out_size;
    const float* x    = (const float*)d_in[0];
    const float* adj  = (const float*)d_in[1];
    const float* Win  = (const float*)d_in[2];
    const float* bin  = (const float*)d_in[3];
    const float* nemb = (const float*)d_in[4];
    const float* gam  = (const float*)d_in[5];
    const float* bet  = (const float*)d_in[6];
    const float* Wg   = (const float*)d_in[7];
    const float* bg   = (const float*)d_in[8];
    float* out = (float*)d_out;

    cudaFuncSetAttribute((const void*)layer_fk<0>,
                         cudaFuncAttributeMaxDynamicSharedMemorySize, SMEMB);
    cudaFuncSetAttribute((const void*)layer_fk<1>,
                         cudaFuncAttributeMaxDynamicSharedMemorySize, SMEMB);

    adj_norm_kernel<<<NNOD, 256>>>(adj);
    wgcvt_kernel<<<(2 * 128 * 256) / 256, 256>>>(Wg);
    zero_kernel<<<TOT / 256, 256>>>();
    pe_kernel<<<6, 256>>>();
    proj_kernel<<<(NBAT * NSEQ * NNOD) / 8, 256>>>(x, Win, bin, nemb, gam, bet);

    dim3 grid(8, NBAT);
    for (int t = 0; t < NSEQ; ++t) {
        int pp = t & 1;
        layer_fk<0><<<grid, 256, SMEMB>>>(t, pp, bg, gam, bet, nemb, out);
        layer_fk<1><<<grid, 256, SMEMB>>>(t, pp, bg, gam, bet, nemb, out);
    }
}